// round 1
// baseline (speedup 1.0000x reference)
#include <cuda_runtime.h>
#include <math.h>

#define NIMG 8
#define CINC 32
#define HH 64
#define WW 64
#define INTER 64
#define BCC 108
#define KS 7
#define NBAS 6
#define TBAS 18
#define OUTC 64
#define NPIX (HH*WW)          // 4096
#define MTOT (NIMG*NPIX)      // 32768
#define EPSV 1e-5f

// ---------------- scratch (device globals; no allocation allowed) ----------
__device__ float g_y1[NIMG*INTER*NPIX];       // conv1 pre-BN output  (8.4 MB)
__device__ float g_y2[NIMG*BCC*NPIX];         // conv2 pre-BN output  (14.2 MB)
__device__ float g_ab1[2*INTER];              // per-channel affine (a,b) for BN1
__device__ float g_ab2[2*BCC];                // per-channel affine (a,b) for BN2
__device__ float g_bout[(long)MTOT*CINC*NBAS];// bases_out, (pix,192) (25 MB)

// ---------------- conv1: x(8,32,64,64) -> y1(8,64,64,64), 3x3 pad1 ---------
__global__ __launch_bounds__(128) void conv1_ker(const float* __restrict__ x,
                                                 const float* __restrict__ w,
                                                 const float* __restrict__ b) {
    // tile: 16 wide x 8 high, 128 threads, one pixel each, 64 out channels
    __shared__ float xt[10*18];     // halo tile for one cin: (8+2) x (16+2)
    __shared__ float wt[INTER*9];
    const int n  = blockIdx.z;
    const int bx = blockIdx.x * 16;
    const int by = blockIdx.y * 8;
    const int tid = threadIdx.x;
    const int px = tid & 15, py = tid >> 4;

    float acc[INTER];
#pragma unroll
    for (int i = 0; i < INTER; i++) acc[i] = 0.f;

    for (int cin = 0; cin < CINC; cin++) {
        for (int i = tid; i < 10*18; i += 128) {
            int yy = i / 18, xx = i % 18;
            int gy = by + yy - 1, gx = bx + xx - 1;
            float v = 0.f;
            if (gy >= 0 && gy < HH && gx >= 0 && gx < WW)
                v = x[((n*CINC + cin)*HH + gy)*WW + gx];
            xt[i] = v;
        }
        for (int i = tid; i < INTER*9; i += 128)
            wt[i] = w[(i/9)*(CINC*9) + cin*9 + (i%9)];
        __syncthreads();

        float xv[9];
#pragma unroll
        for (int dy = 0; dy < 3; dy++)
#pragma unroll
            for (int dx = 0; dx < 3; dx++)
                xv[dy*3+dx] = xt[(py+dy)*18 + (px+dx)];

#pragma unroll
        for (int co = 0; co < INTER; co++) {
            float s = acc[co];
#pragma unroll
            for (int j = 0; j < 9; j++) s = fmaf(xv[j], wt[co*9+j], s);
            acc[co] = s;
        }
        __syncthreads();
    }
    const int gy = by + py, gx = bx + px;
#pragma unroll
    for (int co = 0; co < INTER; co++)
        g_y1[((n*INTER + co)*HH + gy)*WW + gx] = acc[co] + b[co];
}

// ---------------- BN stats: per-channel mean/var -> affine (a,b) -----------
template<int CH, int WHICH>
__global__ __launch_bounds__(256) void stats_ker(const float* __restrict__ gam,
                                                 const float* __restrict__ bet) {
    const float* y = (WHICH == 0) ? g_y1 : g_y2;
    float* ab      = (WHICH == 0) ? g_ab1 : g_ab2;
    const int c = blockIdx.x;
    const int tid = threadIdx.x;
    float s = 0.f, s2 = 0.f;
    for (int i = tid; i < MTOT; i += 256) {
        int nn = i >> 12, p = i & 4095;
        float v = y[(nn*CH + c)*NPIX + p];
        s += v; s2 += v*v;
    }
    __shared__ float sh[256], sh2[256];
    sh[tid] = s; sh2[tid] = s2;
    __syncthreads();
    for (int st = 128; st > 0; st >>= 1) {
        if (tid < st) { sh[tid] += sh[tid+st]; sh2[tid] += sh2[tid+st]; }
        __syncthreads();
    }
    if (tid == 0) {
        float mean = sh[0] * (1.f/(float)MTOT);
        float var  = sh2[0] * (1.f/(float)MTOT) - mean*mean;
        float a = gam[c] * rsqrtf(var + EPSV);
        ab[2*c]   = a;
        ab[2*c+1] = bet[c] - mean * a;
    }
}

// ---------------- conv2: h=tanh(bn1(y1)) -> y2(8,108,64,64), 3x3 pad1 ------
__global__ __launch_bounds__(128) void conv2_ker(const float* __restrict__ w,
                                                 const float* __restrict__ b) {
    // tile 16x8, 128 threads; z = n*2 + half (half selects 54 output channels)
    __shared__ float xt[10*18];
    __shared__ float wt[54*9];
    const int n    = blockIdx.z >> 1;
    const int half = blockIdx.z & 1;
    const int co0  = half * 54;
    const int bx = blockIdx.x * 16;
    const int by = blockIdx.y * 8;
    const int tid = threadIdx.x;
    const int px = tid & 15, py = tid >> 4;

    float acc[54];
#pragma unroll
    for (int i = 0; i < 54; i++) acc[i] = 0.f;

    for (int cin = 0; cin < INTER; cin++) {
        const float a_ = g_ab1[2*cin], b_ = g_ab1[2*cin+1];
        for (int i = tid; i < 10*18; i += 128) {
            int yy = i / 18, xx = i % 18;
            int gy = by + yy - 1, gx = bx + xx - 1;
            float v = 0.f;   // zero padding is applied to h (post-tanh), so OOB -> 0
            if (gy >= 0 && gy < HH && gx >= 0 && gx < WW) {
                float t = g_y1[((n*INTER + cin)*HH + gy)*WW + gx];
                v = tanhf(fmaf(a_, t, b_));
            }
            xt[i] = v;
        }
        for (int i = tid; i < 54*9; i += 128)
            wt[i] = w[(co0 + i/9)*(INTER*9) + cin*9 + (i%9)];
        __syncthreads();

        float xv[9];
#pragma unroll
        for (int dy = 0; dy < 3; dy++)
#pragma unroll
            for (int dx = 0; dx < 3; dx++)
                xv[dy*3+dx] = xt[(py+dy)*18 + (px+dx)];

#pragma unroll
        for (int co = 0; co < 54; co++) {
            float s = acc[co];
#pragma unroll
            for (int j = 0; j < 9; j++) s = fmaf(xv[j], wt[co*9+j], s);
            acc[co] = s;
        }
        __syncthreads();
    }
    const int gy = by + py, gx = bx + px;
#pragma unroll
    for (int co = 0; co < 54; co++)
        g_y2[((n*BCC + co0 + co)*HH + gy)*WW + gx] = acc[co] + b[co0 + co];
}

// -------- fused: coef=tanh(bn2(y2)); atoms=coef@bases; patch contraction ---
// block: 16 pixels (8 wide x 2 high), 256 threads
__global__ __launch_bounds__(256) void atoms_ker(const float* __restrict__ x,
                                                 const float* __restrict__ bases) {
    __shared__ float coef[16*108];     // [pixel][m*18+t]
    __shared__ float atm [16*49*6];    // [pixel][k][m]
    __shared__ float xt  [112*33];     // [pos=yy*14+xx][c], padded c-stride 33
    __shared__ float bs  [TBAS*49];
    const int tid = threadIdx.x;
    const int n  = blockIdx.z;
    const int bx = blockIdx.x * 8;
    const int by = blockIdx.y * 2;

    for (int i = tid; i < TBAS*49; i += 256) bs[i] = bases[i];

    // x halo tile: 14 wide x 8 high x 32 channels, zero-padded
    for (int i = tid; i < 32*112; i += 256) {
        int c = i / 112, pos = i % 112;
        int yy = pos / 14, xx = pos % 14;
        int gy = by + yy - 3, gx = bx + xx - 3;
        float v = 0.f;
        if (gy >= 0 && gy < HH && gx >= 0 && gx < WW)
            v = x[((n*CINC + c)*HH + gy)*WW + gx];
        xt[pos*33 + c] = v;
    }

    // phase A: coef = tanh(bn2(y2))
    for (int i = tid; i < 16*108; i += 256) {
        int p = i / 108, cc = i % 108;
        int py = p >> 3, px = p & 7;
        int gy = by + py, gx = bx + px;
        float v = g_y2[((n*BCC + cc)*HH + gy)*WW + gx];
        coef[i] = tanhf(fmaf(g_ab2[2*cc], v, g_ab2[2*cc+1]));
    }
    __syncthreads();

    // phase B: atoms[p][k][m] = sum_t coef[p][m*18+t] * bases[t][k]
    for (int i = tid; i < 16*49; i += 256) {
        int p = i / 49, k = i % 49;
        const float* cf = &coef[p*108];
        float a0=0,a1=0,a2=0,a3=0,a4=0,a5=0;
#pragma unroll
        for (int t = 0; t < TBAS; t++) {
            float bv = bs[t*49 + k];
            a0 = fmaf(cf[t      ], bv, a0);
            a1 = fmaf(cf[t + 18 ], bv, a1);
            a2 = fmaf(cf[t + 36 ], bv, a2);
            a3 = fmaf(cf[t + 54 ], bv, a3);
            a4 = fmaf(cf[t + 72 ], bv, a4);
            a5 = fmaf(cf[t + 90 ], bv, a5);
        }
        float* ap = &atm[(p*49 + k)*6];
        ap[0]=a0; ap[1]=a1; ap[2]=a2; ap[3]=a3; ap[4]=a4; ap[5]=a5;
    }
    __syncthreads();

    // phase C: bases_out[p][c][m] = sum_k x_patch[c][k] * atoms[p][k][m]
    for (int q = 0; q < 2; q++) {
        int idx = q*256 + tid;
        int p = idx >> 5, c = idx & 31;     // warp-uniform p -> atm broadcast
        int py = p >> 3, px = p & 7;
        const float* ab_ = &atm[p*49*6];
        float a0=0,a1=0,a2=0,a3=0,a4=0,a5=0;
#pragma unroll
        for (int ky = 0; ky < 7; ky++) {
#pragma unroll
            for (int kx = 0; kx < 7; kx++) {
                int k = ky*7 + kx;
                float xv = xt[((py+ky)*14 + (px+kx))*33 + c];
                const float* ap = &ab_[k*6];
                a0 = fmaf(xv, ap[0], a0);
                a1 = fmaf(xv, ap[1], a1);
                a2 = fmaf(xv, ap[2], a2);
                a3 = fmaf(xv, ap[3], a3);
                a4 = fmaf(xv, ap[4], a4);
                a5 = fmaf(xv, ap[5], a5);
            }
        }
        int gy = by + py, gx = bx + px;
        long pix = (long)n*NPIX + gy*WW + gx;
        float* op = &g_bout[pix*192 + c*6];
        op[0]=a0; op[1]=a1; op[2]=a2; op[3]=a3; op[4]=a4; op[5]=a5;
    }
}

// ---------------- out projection: out[n,o,h,w] = W(64,192) . bout + b ------
__global__ __launch_bounds__(256) void out_ker(const float* __restrict__ ow,
                                               const float* __restrict__ ob,
                                               float* __restrict__ out) {
    __shared__ float wt[64*48];        // [o][dl]
    __shared__ float bt[64*49];        // [pix][dl], padded stride 49
    const int pix0 = blockIdx.x * 64;  // 64 consecutive pixels = one image row
    const int tid = threadIdx.x;
    const int pix = tid & 63, og = tid >> 6;   // og in 0..3, 16 outputs each

    float acc[16];
#pragma unroll
    for (int i = 0; i < 16; i++) acc[i] = 0.f;

    for (int ch = 0; ch < 4; ch++) {
        const int d0 = ch * 48;
        for (int i = tid; i < 64*48; i += 256) {
            int o = i / 48, dl = i % 48;
            wt[i] = ow[o*192 + d0 + dl];
        }
        for (int i = tid; i < 64*48; i += 256) {
            int p = i / 48, dl = i % 48;
            bt[p*49 + dl] = g_bout[(long)(pix0 + p)*192 + d0 + dl];
        }
        __syncthreads();
#pragma unroll 4
        for (int dl = 0; dl < 48; dl++) {
            float bv = bt[pix*49 + dl];
#pragma unroll
            for (int i = 0; i < 16; i++)
                acc[i] = fmaf(bv, wt[(og*16 + i)*48 + dl], acc[i]);
        }
        __syncthreads();
    }
    const int n = pix0 >> 12;
    const int rem = (pix0 & 4095) + pix;     // gy*64+gx
#pragma unroll
    for (int i = 0; i < 16; i++) {
        int o = og*16 + i;
        out[((n*OUTC + o)*NPIX) + rem] = acc[i] + ob[o];
    }
}

// ---------------------------------------------------------------------------
extern "C" void kernel_launch(void* const* d_in, const int* in_sizes, int n_in,
                              void* d_out, int out_size) {
    const float* x   = (const float*)d_in[0];
    const float* w1  = (const float*)d_in[1];
    const float* b1  = (const float*)d_in[2];
    const float* g1  = (const float*)d_in[3];
    const float* bb1 = (const float*)d_in[4];
    const float* w2  = (const float*)d_in[5];
    const float* b2  = (const float*)d_in[6];
    const float* g2  = (const float*)d_in[7];
    const float* bb2 = (const float*)d_in[8];
    const float* bas = (const float*)d_in[9];
    const float* ow  = (const float*)d_in[10];
    const float* ob  = (const float*)d_in[11];
    float* out = (float*)d_out;

    conv1_ker<<<dim3(4, 8, NIMG), 128>>>(x, w1, b1);
    stats_ker<INTER, 0><<<INTER, 256>>>(g1, bb1);
    conv2_ker<<<dim3(4, 8, NIMG*2), 128>>>(w2, b2);
    stats_ker<BCC, 1><<<BCC, 256>>>(g2, bb2);
    atoms_ker<<<dim3(8, 32, NIMG), 256>>>(x, bas);
    out_ker<<<512, 256>>>(ow, ob, out);
}

// round 2
// speedup vs baseline: 1.0283x; 1.0283x over previous
#include <cuda_runtime.h>
#include <math.h>

#define NIMG 8
#define CINC 32
#define HH 64
#define WW 64
#define INTER 64
#define BCC 108
#define KS 7
#define NBAS 6
#define TBAS 18
#define OUTC 64
#define NPIX (HH*WW)          // 4096
#define MTOT (NIMG*NPIX)      // 32768
#define EPSV 1e-5f

typedef unsigned long long ull;

// ---------------- f32x2 packed-FMA helpers (sm_103a) -----------------------
__device__ __forceinline__ ull pack2(float lo, float hi) {
    ull r; asm("mov.b64 %0,{%1,%2};" : "=l"(r) : "f"(lo), "f"(hi)); return r;
}
__device__ __forceinline__ void unpack2(ull v, float& lo, float& hi) {
    asm("mov.b64 {%0,%1},%2;" : "=f"(lo), "=f"(hi) : "l"(v));
}
__device__ __forceinline__ ull ffma2(ull a, ull b, ull c) {
    ull d; asm("fma.rn.f32x2 %0,%1,%2,%3;" : "=l"(d) : "l"(a), "l"(b), "l"(c));
    return d;
}

// ---------------- scratch (device globals; no allocation allowed) ----------
__device__ float g_y1[NIMG*INTER*NPIX];        // conv1 out -> h (in-place)
__device__ float g_y2[NIMG*BCC*NPIX];          // conv2 out -> coef (in-place)
__device__ float g_ab1[2*INTER];
__device__ float g_ab2[2*BCC];
__device__ float g_part[2*BCC*NIMG];           // per-(channel,image) stat partials
__device__ float g_bout[(long)MTOT*CINC*NBAS]; // bases_out (pix, 192)

// ---------------- conv1: x(8,32,64,64) -> y1(8,64,64,64), 3x3 pad1 ---------
__global__ __launch_bounds__(128) void conv1_ker(const float* __restrict__ x,
                                                 const float* __restrict__ w,
                                                 const float* __restrict__ b) {
    __shared__ __align__(16) float xt[10*18];
    __shared__ __align__(16) float wt[9*INTER];    // [j][co]
    const int n  = blockIdx.z;
    const int bx = blockIdx.x * 16;
    const int by = blockIdx.y * 8;
    const int tid = threadIdx.x;
    const int px = tid & 15, py = tid >> 4;

    ull acc[32];
#pragma unroll
    for (int i = 0; i < 32; i++) acc[i] = 0ull;

    for (int cin = 0; cin < CINC; cin++) {
        for (int i = tid; i < 10*18; i += 128) {
            int yy = i / 18, xx = i % 18;
            int gy = by + yy - 1, gx = bx + xx - 1;
            float v = 0.f;
            if (gy >= 0 && gy < HH && gx >= 0 && gx < WW)
                v = x[((n*CINC + cin)*HH + gy)*WW + gx];
            xt[i] = v;
        }
        for (int i = tid; i < 9*INTER; i += 128) {
            int j = i >> 6, co = i & 63;
            wt[i] = w[(co*CINC + cin)*9 + j];
        }
        __syncthreads();

        float xv[9];
#pragma unroll
        for (int dy = 0; dy < 3; dy++)
#pragma unroll
            for (int dx = 0; dx < 3; dx++)
                xv[dy*3+dx] = xt[(py+dy)*18 + (px+dx)];

#pragma unroll
        for (int j = 0; j < 9; j++) {
            ull xv2 = pack2(xv[j], xv[j]);
            const ull* wp = (const ull*)&wt[j*INTER];
#pragma unroll
            for (int i = 0; i < 32; i++)
                acc[i] = ffma2(wp[i], xv2, acc[i]);
        }
        __syncthreads();
    }
    const int gy = by + py, gx = bx + px;
#pragma unroll
    for (int i = 0; i < 32; i++) {
        float lo, hi; unpack2(acc[i], lo, hi);
        g_y1[((n*INTER + 2*i  )*HH + gy)*WW + gx] = lo + b[2*i];
        g_y1[((n*INTER + 2*i+1)*HH + gy)*WW + gx] = hi + b[2*i+1];
    }
}

// ---------------- BN stats: per-(channel,image) partials -------------------
template<int CH, int WHICH>
__global__ __launch_bounds__(256) void stats_part() {
    const float* y = (WHICH == 0) ? g_y1 : g_y2;
    const int c = blockIdx.x, n = blockIdx.y;
    const int tid = threadIdx.x;
    const float4* p4 = (const float4*)&y[(size_t)(n*CH + c)*NPIX];
    float s = 0.f, s2 = 0.f;
#pragma unroll
    for (int i = tid; i < NPIX/4; i += 256) {
        float4 f = p4[i];
        s  += (f.x + f.y) + (f.z + f.w);
        s2 += (f.x*f.x + f.y*f.y) + (f.z*f.z + f.w*f.w);
    }
    __shared__ float sh[256], sh2[256];
    sh[tid] = s; sh2[tid] = s2;
    __syncthreads();
    for (int st = 128; st > 0; st >>= 1) {
        if (tid < st) { sh[tid] += sh[tid+st]; sh2[tid] += sh2[tid+st]; }
        __syncthreads();
    }
    if (tid == 0) {
        g_part[c*NIMG + n] = sh[0];
        g_part[BCC*NIMG + c*NIMG + n] = sh2[0];
    }
}

template<int CH, int WHICH>
__global__ __launch_bounds__(128) void stats_fin(const float* __restrict__ gam,
                                                 const float* __restrict__ bet) {
    float* ab = (WHICH == 0) ? g_ab1 : g_ab2;
    const int c = threadIdx.x;
    if (c >= CH) return;
    float s = 0.f, s2 = 0.f;
#pragma unroll
    for (int n = 0; n < NIMG; n++) {
        s  += g_part[c*NIMG + n];
        s2 += g_part[BCC*NIMG + c*NIMG + n];
    }
    float mean = s * (1.f/(float)MTOT);
    float var  = s2 * (1.f/(float)MTOT) - mean*mean;
    float a = gam[c] * rsqrtf(var + EPSV);
    ab[2*c]   = a;
    ab[2*c+1] = bet[c] - mean * a;
}

// ---------------- elementwise: y = tanh(a*y + b), in place -----------------
template<int CH, int WHICH>
__global__ __launch_bounds__(256) void bn_tanh_ker() {
    float* y = (WHICH == 0) ? g_y1 : g_y2;
    const float* ab = (WHICH == 0) ? g_ab1 : g_ab2;
    const int i = blockIdx.x * 256 + threadIdx.x;      // float4 index
    const int c = (i >> 10) % CH;                      // 1024 float4 per (n,c)
    const float a = ab[2*c], b = ab[2*c+1];
    float4* p4 = (float4*)y;
    float4 f = p4[i];
    f.x = tanhf(fmaf(a, f.x, b));
    f.y = tanhf(fmaf(a, f.y, b));
    f.z = tanhf(fmaf(a, f.z, b));
    f.w = tanhf(fmaf(a, f.w, b));
    p4[i] = f;
}

// ---------------- conv2: h(8,64,64,64) -> y2(8,108,64,64), 3x3 pad1 --------
__global__ __launch_bounds__(128) void conv2_ker(const float* __restrict__ w,
                                                 const float* __restrict__ b) {
    __shared__ __align__(16) float xt[10*18];
    __shared__ __align__(16) float wt[9*54];       // [j][co]
    const int n    = blockIdx.z >> 1;
    const int half = blockIdx.z & 1;
    const int co0  = half * 54;
    const int bx = blockIdx.x * 16;
    const int by = blockIdx.y * 8;
    const int tid = threadIdx.x;
    const int px = tid & 15, py = tid >> 4;

    ull acc[27];
#pragma unroll
    for (int i = 0; i < 27; i++) acc[i] = 0ull;

    for (int cin = 0; cin < INTER; cin++) {
        for (int i = tid; i < 10*18; i += 128) {
            int yy = i / 18, xx = i % 18;
            int gy = by + yy - 1, gx = bx + xx - 1;
            float v = 0.f;
            if (gy >= 0 && gy < HH && gx >= 0 && gx < WW)
                v = g_y1[((n*INTER + cin)*HH + gy)*WW + gx];
            xt[i] = v;
        }
        for (int i = tid; i < 9*54; i += 128) {
            int j = i / 54, co = i % 54;
            wt[i] = w[((co0 + co)*INTER + cin)*9 + j];
        }
        __syncthreads();

        float xv[9];
#pragma unroll
        for (int dy = 0; dy < 3; dy++)
#pragma unroll
            for (int dx = 0; dx < 3; dx++)
                xv[dy*3+dx] = xt[(py+dy)*18 + (px+dx)];

#pragma unroll
        for (int j = 0; j < 9; j++) {
            ull xv2 = pack2(xv[j], xv[j]);
            const ull* wp = (const ull*)&wt[j*54];
#pragma unroll
            for (int i = 0; i < 27; i++)
                acc[i] = ffma2(wp[i], xv2, acc[i]);
        }
        __syncthreads();
    }
    const int gy = by + py, gx = bx + px;
#pragma unroll
    for (int i = 0; i < 27; i++) {
        float lo, hi; unpack2(acc[i], lo, hi);
        g_y2[((n*BCC + co0 + 2*i  )*HH + gy)*WW + gx] = lo + b[co0 + 2*i];
        g_y2[((n*BCC + co0 + 2*i+1)*HH + gy)*WW + gx] = hi + b[co0 + 2*i+1];
    }
}

// -------- fused: coef (pre-tanh'd) -> atoms -> 7x7 patch contraction -------
__global__ __launch_bounds__(256) void atoms_ker(const float* __restrict__ x,
                                                 const float* __restrict__ bases) {
    __shared__ __align__(16) float coef[16*108];   // [pixel][m*18+t]
    __shared__ __align__(16) float atm [16*49*6];  // [pixel][k][m]
    __shared__ __align__(16) float xt  [112*33];   // [pos][c], padded stride 33
    __shared__ __align__(16) float bs2 [49*TBAS];  // transposed: [k][t]
    const int tid = threadIdx.x;
    const int n  = blockIdx.z;
    const int bx = blockIdx.x * 8;
    const int by = blockIdx.y * 2;

    for (int i = tid; i < 49*TBAS; i += 256) {
        int k = i / TBAS, t = i % TBAS;
        bs2[i] = bases[t*49 + k];
    }

    // x halo tile: 14 wide x 8 high x 32 channels, zero-padded
    for (int i = tid; i < 32*112; i += 256) {
        int c = i / 112, pos = i % 112;
        int yy = pos / 14, xx = pos % 14;
        int gy = by + yy - 3, gx = bx + xx - 3;
        float v = 0.f;
        if (gy >= 0 && gy < HH && gx >= 0 && gx < WW)
            v = x[((n*CINC + c)*HH + gy)*WW + gx];
        xt[pos*33 + c] = v;
    }

    // phase A: stage coef (already tanh(bn(.)) in g_y2)
    for (int i = tid; i < 16*108; i += 256) {
        int p = i / 108, cc = i % 108;
        int py = p >> 3, px = p & 7;
        coef[i] = g_y2[((n*BCC + cc)*HH + (by+py))*WW + (bx+px)];
    }
    __syncthreads();

    // phase B: atoms[p][k][m] = sum_t coef[p][m*18+t] * bases[t][k]  (f32x2 over t)
    for (int i = tid; i < 16*49; i += 256) {
        int p = i / 49, k = i % 49;
        const ull* cf = (const ull*)&coef[p*108];
        const ull* bp = (const ull*)&bs2[k*TBAS];
        ull a[6];
#pragma unroll
        for (int m = 0; m < 6; m++) a[m] = 0ull;
#pragma unroll
        for (int u = 0; u < 9; u++) {
            ull bv = bp[u];
#pragma unroll
            for (int m = 0; m < 6; m++)
                a[m] = ffma2(cf[m*9 + u], bv, a[m]);
        }
        float* ap = &atm[(p*49 + k)*6];
#pragma unroll
        for (int m = 0; m < 6; m++) {
            float lo, hi; unpack2(a[m], lo, hi);
            ap[m] = lo + hi;
        }
    }
    __syncthreads();

    // phase C: bases_out[p][c][m] = sum_k x_patch[c][k] * atoms[p][k][m]  (f32x2 over m)
    for (int q = 0; q < 2; q++) {
        int idx = q*256 + tid;
        int p = idx >> 5, c = idx & 31;     // warp-uniform p -> atm broadcast
        int py = p >> 3, px = p & 7;
        const float* ab_ = &atm[p*49*6];
        ull a01 = 0ull, a23 = 0ull, a45 = 0ull;
#pragma unroll
        for (int ky = 0; ky < 7; ky++) {
#pragma unroll
            for (int kx = 0; kx < 7; kx++) {
                int k = ky*7 + kx;
                float xv = xt[((py+ky)*14 + (px+kx))*33 + c];
                ull xv2 = pack2(xv, xv);
                const ull* ap = (const ull*)&ab_[k*6];
                a01 = ffma2(ap[0], xv2, a01);
                a23 = ffma2(ap[1], xv2, a23);
                a45 = ffma2(ap[2], xv2, a45);
            }
        }
        int gy = by + py, gx = bx + px;
        long pix = (long)n*NPIX + gy*WW + gx;
        ull* op = (ull*)&g_bout[pix*192 + c*6];
        op[0] = a01; op[1] = a23; op[2] = a45;
    }
}

// ---------------- out projection: out = W(64,192) . bout + b ---------------
__global__ __launch_bounds__(256) void out_ker(const float* __restrict__ ow,
                                               const float* __restrict__ ob,
                                               float* __restrict__ out) {
    __shared__ __align__(16) float wt2[48*64];   // [dl][o]
    __shared__ __align__(16) float bt[64*49];    // [pix][dl], padded stride 49
    const int pix0 = blockIdx.x * 64;            // one image row
    const int tid = threadIdx.x;
    const int pix = tid & 63, og = tid >> 6;     // og 0..3, 16 outputs each

    ull acc2[8];
#pragma unroll
    for (int i = 0; i < 8; i++) acc2[i] = 0ull;

    for (int ch = 0; ch < 4; ch++) {
        const int d0 = ch * 48;
        for (int i = tid; i < 48*64; i += 256) {
            int dl = i >> 6, o = i & 63;
            wt2[i] = ow[o*192 + d0 + dl];
        }
        for (int i = tid; i < 64*12; i += 256) {
            int p = i / 12, v = i % 12;
            float4 f = ((const float4*)&g_bout[(long)(pix0 + p)*192 + d0])[v];
            float* dst = &bt[p*49 + v*4];
            dst[0] = f.x; dst[1] = f.y; dst[2] = f.z; dst[3] = f.w;
        }
        __syncthreads();
#pragma unroll 4
        for (int dl = 0; dl < 48; dl++) {
            float bv = bt[pix*49 + dl];
            ull bv2 = pack2(bv, bv);
            const ull* wp = (const ull*)&wt2[dl*64 + og*16];
#pragma unroll
            for (int i = 0; i < 8; i++)
                acc2[i] = ffma2(wp[i], bv2, acc2[i]);
        }
        __syncthreads();
    }
    const int n = pix0 >> 12;
    const int rem = (pix0 & 4095) + pix;
#pragma unroll
    for (int i = 0; i < 8; i++) {
        float lo, hi; unpack2(acc2[i], lo, hi);
        int o = og*16 + 2*i;
        out[((n*OUTC + o  )*NPIX) + rem] = lo + ob[o];
        out[((n*OUTC + o+1)*NPIX) + rem] = hi + ob[o+1];
    }
}

// ---------------------------------------------------------------------------
extern "C" void kernel_launch(void* const* d_in, const int* in_sizes, int n_in,
                              void* d_out, int out_size) {
    const float* x   = (const float*)d_in[0];
    const float* w1  = (const float*)d_in[1];
    const float* b1  = (const float*)d_in[2];
    const float* g1  = (const float*)d_in[3];
    const float* bb1 = (const float*)d_in[4];
    const float* w2  = (const float*)d_in[5];
    const float* b2  = (const float*)d_in[6];
    const float* g2  = (const float*)d_in[7];
    const float* bb2 = (const float*)d_in[8];
    const float* bas = (const float*)d_in[9];
    const float* ow  = (const float*)d_in[10];
    const float* ob  = (const float*)d_in[11];
    float* out = (float*)d_out;

    conv1_ker<<<dim3(4, 8, NIMG), 128>>>(x, w1, b1);
    stats_part<INTER, 0><<<dim3(INTER, NIMG), 256>>>();
    stats_fin<INTER, 0><<<1, 128>>>(g1, bb1);
    bn_tanh_ker<INTER, 0><<<(NIMG*INTER*NPIX/4)/256, 256>>>();
    conv2_ker<<<dim3(4, 8, NIMG*2), 128>>>(w2, b2);
    stats_part<BCC, 1><<<dim3(BCC, NIMG), 256>>>();
    stats_fin<BCC, 1><<<1, 128>>>(g2, bb2);
    bn_tanh_ker<BCC, 1><<<(NIMG*BCC*NPIX/4)/256, 256>>>();
    atoms_ker<<<dim3(8, 32, NIMG), 256>>>(x, bas);
    out_ker<<<512, 256>>>(ow, ob, out);
}

// round 3
// speedup vs baseline: 1.1799x; 1.1474x over previous
#include <cuda_runtime.h>
#include <math.h>

#define NIMG 8
#define CINC 32
#define HH 64
#define WW 64
#define INTER 64
#define BCC 108
#define KS 7
#define NBAS 6
#define TBAS 18
#define OUTC 64
#define NPIX (HH*WW)          // 4096
#define MTOT (NIMG*NPIX)      // 32768
#define EPSV 1e-5f

typedef unsigned long long ull;

// ---------------- f32x2 packed-FMA helpers (sm_103a) -----------------------
__device__ __forceinline__ ull pack2(float lo, float hi) {
    ull r; asm("mov.b64 %0,{%1,%2};" : "=l"(r) : "f"(lo), "f"(hi)); return r;
}
__device__ __forceinline__ void unpack2(ull v, float& lo, float& hi) {
    asm("mov.b64 {%0,%1},%2;" : "=f"(lo), "=f"(hi) : "l"(v));
}
__device__ __forceinline__ ull ffma2(ull a, ull b, ull c) {
    ull d; asm("fma.rn.f32x2 %0,%1,%2,%3;" : "=l"(d) : "l"(a), "l"(b), "l"(c));
    return d;
}

// ---------------- scratch ---------------------------------------------------
__device__ float g_y1[NIMG*INTER*NPIX];
__device__ float g_y2[NIMG*BCC*NPIX];
__device__ float g_ab1[2*INTER];
__device__ float g_ab2[2*BCC];
__device__ float g_part[2*BCC*NIMG];
__device__ float g_bout[(long)MTOT*CINC*NBAS];

// ======================= conv1: 32ch -> 64ch, 3x3 pad1 ======================
// block: 256 thr, pixel tile 32x8; blockIdx.z = n*4 + cg (cg: 16-ch group)
__global__ __launch_bounds__(256) void conv1_ker(const float* __restrict__ x,
                                                 const float* __restrict__ w,
                                                 const float* __restrict__ b) {
    __shared__ __align__(16) float xt[8*340];      // [ci][10][34]
    __shared__ __align__(16) float wt[8*9*16];     // [ci][j][16co]
    const int n  = blockIdx.z >> 2;
    const int cg = blockIdx.z & 3;
    const int co0 = cg * 16;
    const int bx = blockIdx.x * 32;
    const int by = blockIdx.y * 8;
    const int tid = threadIdx.x;
    const int px = tid & 31, py = tid >> 5;

    ull acc[8];
#pragma unroll
    for (int i = 0; i < 8; i++) acc[i] = 0ull;

    for (int ch = 0; ch < CINC; ch += 8) {
        for (int i = tid; i < 8*340; i += 256) {
            int ci = i / 340, rem = i % 340;
            int yy = rem / 34, xx = rem % 34;
            int gy = by + yy - 1, gx = bx + xx - 1;
            float v = 0.f;
            if (gy >= 0 && gy < HH && gx >= 0 && gx < WW)
                v = x[((n*CINC + ch + ci)*HH + gy)*WW + gx];
            xt[i] = v;
        }
        for (int i = tid; i < 8*9*16; i += 256) {
            int ci = i / 144, rem = i % 144;
            int j = rem >> 4, col = rem & 15;
            wt[i] = w[((co0 + col)*CINC + ch + ci)*9 + j];
        }
        __syncthreads();

#pragma unroll
        for (int ci = 0; ci < 8; ci++) {
            ull xv2[9];
#pragma unroll
            for (int dy = 0; dy < 3; dy++)
#pragma unroll
                for (int dx = 0; dx < 3; dx++) {
                    float v = xt[ci*340 + (py+dy)*34 + (px+dx)];
                    xv2[dy*3+dx] = pack2(v, v);
                }
#pragma unroll
            for (int j = 0; j < 9; j++) {
                const ulonglong2* wp = (const ulonglong2*)&wt[(ci*9 + j)*16];
#pragma unroll
                for (int q = 0; q < 4; q++) {
                    ulonglong2 u = wp[q];
                    acc[2*q  ] = ffma2(u.x, xv2[j], acc[2*q  ]);
                    acc[2*q+1] = ffma2(u.y, xv2[j], acc[2*q+1]);
                }
            }
        }
        __syncthreads();
    }
    const int gy = by + py, gx = bx + px;
#pragma unroll
    for (int i = 0; i < 8; i++) {
        float lo, hi; unpack2(acc[i], lo, hi);
        int co = co0 + 2*i;
        g_y1[((n*INTER + co  )*HH + gy)*WW + gx] = lo + b[co];
        g_y1[((n*INTER + co+1)*HH + gy)*WW + gx] = hi + b[co+1];
    }
}

// ======================= conv2: 64ch -> 108ch, 3x3 pad1 =====================
// block: 256 thr, tile 32x8; blockIdx.z = n*4 + cg (cg: 27-ch group, pad 28)
__global__ __launch_bounds__(256) void conv2_ker(const float* __restrict__ w,
                                                 const float* __restrict__ b) {
    __shared__ __align__(16) float xt[8*340];
    __shared__ __align__(16) float wt[8*9*28];     // [ci][j][28co]
    const int n  = blockIdx.z >> 2;
    const int cg = blockIdx.z & 3;
    const int co0 = cg * 27;
    const int bx = blockIdx.x * 32;
    const int by = blockIdx.y * 8;
    const int tid = threadIdx.x;
    const int px = tid & 31, py = tid >> 5;

    ull acc[14];
#pragma unroll
    for (int i = 0; i < 14; i++) acc[i] = 0ull;

    for (int ch = 0; ch < INTER; ch += 8) {
        for (int i = tid; i < 8*340; i += 256) {
            int ci = i / 340, rem = i % 340;
            int yy = rem / 34, xx = rem % 34;
            int gy = by + yy - 1, gx = bx + xx - 1;
            float v = 0.f;
            if (gy >= 0 && gy < HH && gx >= 0 && gx < WW)
                v = g_y1[((n*INTER + ch + ci)*HH + gy)*WW + gx];
            xt[i] = v;
        }
        for (int i = tid; i < 8*9*28; i += 256) {
            int ci = i / 252, rem = i % 252;
            int j = rem / 28, col = rem % 28;
            wt[i] = (col < 27) ? w[((co0 + col)*INTER + ch + ci)*9 + j] : 0.f;
        }
        __syncthreads();

#pragma unroll
        for (int ci = 0; ci < 8; ci++) {
            ull xv2[9];
#pragma unroll
            for (int dy = 0; dy < 3; dy++)
#pragma unroll
                for (int dx = 0; dx < 3; dx++) {
                    float v = xt[ci*340 + (py+dy)*34 + (px+dx)];
                    xv2[dy*3+dx] = pack2(v, v);
                }
#pragma unroll
            for (int j = 0; j < 9; j++) {
                const ulonglong2* wp = (const ulonglong2*)&wt[(ci*9 + j)*28];
#pragma unroll
                for (int q = 0; q < 7; q++) {
                    ulonglong2 u = wp[q];
                    acc[2*q  ] = ffma2(u.x, xv2[j], acc[2*q  ]);
                    acc[2*q+1] = ffma2(u.y, xv2[j], acc[2*q+1]);
                }
            }
        }
        __syncthreads();
    }
    const int gy = by + py, gx = bx + px;
#pragma unroll
    for (int i = 0; i < 14; i++) {
        float lo, hi; unpack2(acc[i], lo, hi);
        int cl = 2*i;
        if (cl < 27)
            g_y2[((n*BCC + co0 + cl)*HH + gy)*WW + gx] = lo + b[co0 + cl];
        if (cl + 1 < 27)
            g_y2[((n*BCC + co0 + cl+1)*HH + gy)*WW + gx] = hi + b[co0 + cl+1];
    }
}

// ---------------- BN stats: partials + finalize -----------------------------
template<int CH, int WHICH>
__global__ __launch_bounds__(256) void stats_part() {
    const float* y = (WHICH == 0) ? g_y1 : g_y2;
    const int c = blockIdx.x, n = blockIdx.y;
    const int tid = threadIdx.x;
    const float4* p4 = (const float4*)&y[(size_t)(n*CH + c)*NPIX];
    float s = 0.f, s2 = 0.f;
#pragma unroll
    for (int k = 0; k < 4; k++) {
        float4 f = p4[k*256 + tid];
        s  += (f.x + f.y) + (f.z + f.w);
        s2 += (f.x*f.x + f.y*f.y) + (f.z*f.z + f.w*f.w);
    }
    __shared__ float sh[256], sh2[256];
    sh[tid] = s; sh2[tid] = s2;
    __syncthreads();
    for (int st = 128; st > 0; st >>= 1) {
        if (tid < st) { sh[tid] += sh[tid+st]; sh2[tid] += sh2[tid+st]; }
        __syncthreads();
    }
    if (tid == 0) {
        g_part[c*NIMG + n] = sh[0];
        g_part[BCC*NIMG + c*NIMG + n] = sh2[0];
    }
}

template<int CH, int WHICH>
__global__ __launch_bounds__(128) void stats_fin(const float* __restrict__ gam,
                                                 const float* __restrict__ bet) {
    float* ab = (WHICH == 0) ? g_ab1 : g_ab2;
    const int c = threadIdx.x;
    if (c >= CH) return;
    float s = 0.f, s2 = 0.f;
#pragma unroll
    for (int n = 0; n < NIMG; n++) {
        s  += g_part[c*NIMG + n];
        s2 += g_part[BCC*NIMG + c*NIMG + n];
    }
    float mean = s * (1.f/(float)MTOT);
    float var  = s2 * (1.f/(float)MTOT) - mean*mean;
    float a = gam[c] * rsqrtf(var + EPSV);
    ab[2*c]   = a;
    ab[2*c+1] = bet[c] - mean * a;
}

// ---------------- y = tanh(a*y + b) in place; one block per (n,c) ----------
template<int CH, int WHICH>
__global__ __launch_bounds__(256) void bn_tanh_ker() {
    float* y = (WHICH == 0) ? g_y1 : g_y2;
    const float* ab = (WHICH == 0) ? g_ab1 : g_ab2;
    const int c = blockIdx.x % CH;
    const float a = ab[2*c], b = ab[2*c+1];
    float4* p4 = (float4*)y + (size_t)blockIdx.x * 1024;
#pragma unroll
    for (int k = 0; k < 4; k++) {
        float4 f = p4[k*256 + threadIdx.x];
        f.x = tanhf(fmaf(a, f.x, b));
        f.y = tanhf(fmaf(a, f.y, b));
        f.z = tanhf(fmaf(a, f.z, b));
        f.w = tanhf(fmaf(a, f.w, b));
        p4[k*256 + threadIdx.x] = f;
    }
}

// -------- fused: coef -> atoms -> 7x7 patch contraction --------------------
__global__ __launch_bounds__(256) void atoms_ker(const float* __restrict__ x,
                                                 const float* __restrict__ bases) {
    __shared__ __align__(16) float coef[16*108];
    __shared__ __align__(16) float atm [16*49*6];
    __shared__ __align__(16) float xt  [112*33];
    __shared__ __align__(16) float bs2 [49*TBAS];
    const int tid = threadIdx.x;
    const int n  = blockIdx.z;
    const int bx = blockIdx.x * 8;
    const int by = blockIdx.y * 2;

    for (int i = tid; i < 49*TBAS; i += 256) {
        int k = i / TBAS, t = i % TBAS;
        bs2[i] = bases[t*49 + k];
    }
    for (int i = tid; i < 32*112; i += 256) {
        int c = i / 112, pos = i % 112;
        int yy = pos / 14, xx = pos % 14;
        int gy = by + yy - 3, gx = bx + xx - 3;
        float v = 0.f;
        if (gy >= 0 && gy < HH && gx >= 0 && gx < WW)
            v = x[((n*CINC + c)*HH + gy)*WW + gx];
        xt[pos*33 + c] = v;
    }
    for (int i = tid; i < 16*108; i += 256) {
        int p = i / 108, cc = i % 108;
        int py = p >> 3, px = p & 7;
        coef[i] = g_y2[((n*BCC + cc)*HH + (by+py))*WW + (bx+px)];
    }
    __syncthreads();

    for (int i = tid; i < 16*49; i += 256) {
        int p = i / 49, k = i % 49;
        const ull* cf = (const ull*)&coef[p*108];
        const ull* bp = (const ull*)&bs2[k*TBAS];
        ull a[6];
#pragma unroll
        for (int m = 0; m < 6; m++) a[m] = 0ull;
#pragma unroll
        for (int u = 0; u < 9; u++) {
            ull bv = bp[u];
#pragma unroll
            for (int m = 0; m < 6; m++)
                a[m] = ffma2(cf[m*9 + u], bv, a[m]);
        }
        float* ap = &atm[(p*49 + k)*6];
#pragma unroll
        for (int m = 0; m < 6; m++) {
            float lo, hi; unpack2(a[m], lo, hi);
            ap[m] = lo + hi;
        }
    }
    __syncthreads();

#pragma unroll
    for (int q = 0; q < 2; q++) {
        int idx = q*256 + tid;
        int p = idx >> 5, c = idx & 31;
        int py = p >> 3, px = p & 7;
        const float* ab_ = &atm[p*49*6];
        ull a01 = 0ull, a23 = 0ull, a45 = 0ull;
#pragma unroll
        for (int ky = 0; ky < 7; ky++) {
#pragma unroll
            for (int kx = 0; kx < 7; kx++) {
                int k = ky*7 + kx;
                float xv = xt[((py+ky)*14 + (px+kx))*33 + c];
                ull xv2 = pack2(xv, xv);
                const ull* ap = (const ull*)&ab_[k*6];
                a01 = ffma2(ap[0], xv2, a01);
                a23 = ffma2(ap[1], xv2, a23);
                a45 = ffma2(ap[2], xv2, a45);
            }
        }
        int gy = by + py, gx = bx + px;
        long pix = (long)n*NPIX + gy*WW + gx;
        ull* op = (ull*)&g_bout[pix*192 + c*6];
        op[0] = a01; op[1] = a23; op[2] = a45;
    }
}

// ---------------- out projection: out = W(64,192) . bout + b ---------------
__global__ __launch_bounds__(256) void out_ker(const float* __restrict__ ow,
                                               const float* __restrict__ ob,
                                               float* __restrict__ out) {
    __shared__ __align__(16) float wt2[48*64];   // [dl][o]
    __shared__ __align__(16) float bt[64*49];    // [pix][dl], pad 49
    const int pix0 = blockIdx.x * 64;
    const int tid = threadIdx.x;
    const int pix = tid & 63, og = tid >> 6;

    ull acc2[8];
#pragma unroll
    for (int i = 0; i < 8; i++) acc2[i] = 0ull;

    for (int ch = 0; ch < 4; ch++) {
        const int d0 = ch * 48;
        for (int i = tid; i < 48*64; i += 256) {
            int dl = i >> 6, o = i & 63;
            wt2[i] = ow[o*192 + d0 + dl];
        }
        for (int i = tid; i < 64*12; i += 256) {
            int p = i / 12, v = i % 12;
            float4 f = ((const float4*)&g_bout[(long)(pix0 + p)*192 + d0])[v];
            float* dst = &bt[p*49 + v*4];
            dst[0] = f.x; dst[1] = f.y; dst[2] = f.z; dst[3] = f.w;
        }
        __syncthreads();
#pragma unroll 4
        for (int dl = 0; dl < 48; dl++) {
            float bv = bt[pix*49 + dl];
            ull bv2 = pack2(bv, bv);
            const ulonglong2* wp = (const ulonglong2*)&wt2[dl*64 + og*16];
#pragma unroll
            for (int q = 0; q < 4; q++) {
                ulonglong2 u = wp[q];
                acc2[2*q  ] = ffma2(u.x, bv2, acc2[2*q  ]);
                acc2[2*q+1] = ffma2(u.y, bv2, acc2[2*q+1]);
            }
        }
        __syncthreads();
    }
    const int n = pix0 >> 12;
    const int rem = (pix0 & 4095) + pix;
#pragma unroll
    for (int i = 0; i < 8; i++) {
        float lo, hi; unpack2(acc2[i], lo, hi);
        int o = og*16 + 2*i;
        out[((n*OUTC + o  )*NPIX) + rem] = lo + ob[o];
        out[((n*OUTC + o+1)*NPIX) + rem] = hi + ob[o+1];
    }
}

// ---------------------------------------------------------------------------
extern "C" void kernel_launch(void* const* d_in, const int* in_sizes, int n_in,
                              void* d_out, int out_size) {
    const float* x   = (const float*)d_in[0];
    const float* w1  = (const float*)d_in[1];
    const float* b1  = (const float*)d_in[2];
    const float* g1  = (const float*)d_in[3];
    const float* bb1 = (const float*)d_in[4];
    const float* w2  = (const float*)d_in[5];
    const float* b2  = (const float*)d_in[6];
    const float* g2  = (const float*)d_in[7];
    const float* bb2 = (const float*)d_in[8];
    const float* bas = (const float*)d_in[9];
    const float* ow  = (const float*)d_in[10];
    const float* ob  = (const float*)d_in[11];
    float* out = (float*)d_out;

    conv1_ker<<<dim3(2, 8, NIMG*4), 256>>>(x, w1, b1);
    stats_part<INTER, 0><<<dim3(INTER, NIMG), 256>>>();
    stats_fin<INTER, 0><<<1, 128>>>(g1, bb1);
    bn_tanh_ker<INTER, 0><<<NIMG*INTER, 256>>>();
    conv2_ker<<<dim3(2, 8, NIMG*4), 256>>>(w2, b2);
    stats_part<BCC, 1><<<dim3(BCC, NIMG), 256>>>();
    stats_fin<BCC, 1><<<1, 128>>>(g2, bb2);
    bn_tanh_ker<BCC, 1><<<NIMG*BCC, 256>>>();
    atoms_ker<<<dim3(8, 32, NIMG), 256>>>(x, bas);
    out_ker<<<512, 256>>>(ow, ob, out);
}